// round 1
// baseline (speedup 1.0000x reference)
#include <cuda_runtime.h>
#include <cstdint>

// Problem constants
#define MPTS   131072      // total points
#define NSEG   32
#define SEGSZ  (MPTS / NSEG)   // 4096

#define BM 128
#define BN 128
#define BK 16

// Scratch intermediates (device globals — no allocation allowed)
__device__ float g_h1[(size_t)MPTS * 256];   // 134 MB
__device__ float g_h2[(size_t)MPTS * 512];   // 268 MB

__global__ void zero_out_kernel(float* out, int n) {
    int i = blockIdx.x * blockDim.x + threadIdx.x;
    if (i < n) out[i] = 0.0f;
}

// Generic fused GEMM: C = relu(A @ B + bias)
//  CONCAT_A: A is the virtual concat [x | pos] with K=259 (A = x, lda=256; pos separate)
//  SEGMAX:   instead of storing C, reduce max over the 128-row tile and atomicMax
//            into C[seg*N + col] (values are >=0 so int-punned atomicMax is order-correct)
template<bool CONCAT_A, bool SEGMAX>
__global__ __launch_bounds__(256, 2)
void mlp_gemm(const float* __restrict__ A, const float* __restrict__ pos,
              const float* __restrict__ B, const float* __restrict__ bias,
              const int* __restrict__ batch,
              float* __restrict__ C, int N, int K, int lda)
{
    __shared__ float As[BK][BM];   // 8 KB
    __shared__ float Bs[BK][BN];   // 8 KB

    const int tid = threadIdx.x;
    const int tx = tid & 15;       // 0..15 -> columns
    const int ty = tid >> 4;       // 0..15 -> rows
    const int row0 = blockIdx.y * BM;
    const int col0 = blockIdx.x * BN;

    float acc[8][8];
#pragma unroll
    for (int i = 0; i < 8; i++)
#pragma unroll
        for (int j = 0; j < 8; j++) acc[i][j] = 0.0f;

    const int nCh = (K + BK - 1) / BK;
    for (int ch = 0; ch < nCh; ch++) {
        const int kb = ch * BK;

        // ---- load A tile -> As[k][m] ----
        if (CONCAT_A) {
#pragma unroll
            for (int t = 0; t < 8; t++) {
                int lin = t * 256 + tid;      // 0..2047
                int m = lin >> 4;
                int k = lin & 15;
                int gk = kb + k;
                float v = 0.0f;
                int r = row0 + m;
                if (gk < 256)      v = A[(size_t)r * 256 + gk];
                else if (gk < 259) v = pos[(size_t)r * 3 + (gk - 256)];
                As[k][m] = v;
            }
        } else {
#pragma unroll
            for (int t = 0; t < 2; t++) {
                int lin = t * 256 + tid;      // 0..511 float4 slots
                int m  = lin >> 2;
                int k4 = lin & 3;
                float4 v = *(const float4*)&A[(size_t)(row0 + m) * lda + kb + k4 * 4];
                As[k4 * 4 + 0][m] = v.x;
                As[k4 * 4 + 1][m] = v.y;
                As[k4 * 4 + 2][m] = v.z;
                As[k4 * 4 + 3][m] = v.w;
            }
        }

        // ---- load B tile (row-major [K,N]) -> Bs[k][n] ----
#pragma unroll
        for (int t = 0; t < 2; t++) {
            int lin = t * 256 + tid;          // 0..511 float4 slots
            int k  = lin >> 5;                // 32 float4 per 128-wide row
            int n4 = lin & 31;
            int gk = kb + k;
            float4 v = make_float4(0.f, 0.f, 0.f, 0.f);
            if (gk < K) v = *(const float4*)&B[(size_t)gk * N + col0 + n4 * 4];
            *(float4*)&Bs[k][n4 * 4] = v;
        }
        __syncthreads();

        // ---- compute ----
#pragma unroll
        for (int k = 0; k < BK; k++) {
            float ra[8], rb[8];
            *(float4*)&ra[0] = *(float4*)&As[k][ty * 4];
            *(float4*)&ra[4] = *(float4*)&As[k][64 + ty * 4];
            *(float4*)&rb[0] = *(float4*)&Bs[k][tx * 4];
            *(float4*)&rb[4] = *(float4*)&Bs[k][64 + tx * 4];
#pragma unroll
            for (int i = 0; i < 8; i++)
#pragma unroll
                for (int j = 0; j < 8; j++)
                    acc[i][j] += ra[i] * rb[j];
        }
        __syncthreads();
    }

    // ---- epilogue ----
    float4 bv0 = *(const float4*)&bias[col0 + tx * 4];
    float4 bv1 = *(const float4*)&bias[col0 + 64 + tx * 4];
    float bj[8] = {bv0.x, bv0.y, bv0.z, bv0.w, bv1.x, bv1.y, bv1.z, bv1.w};

    if (!SEGMAX) {
#pragma unroll
        for (int i = 0; i < 8; i++) {
            int r = row0 + ((i < 4) ? (ty * 4 + i) : (64 + ty * 4 + i - 4));
            float4 o0, o1;
            o0.x = fmaxf(acc[i][0] + bj[0], 0.f);
            o0.y = fmaxf(acc[i][1] + bj[1], 0.f);
            o0.z = fmaxf(acc[i][2] + bj[2], 0.f);
            o0.w = fmaxf(acc[i][3] + bj[3], 0.f);
            o1.x = fmaxf(acc[i][4] + bj[4], 0.f);
            o1.y = fmaxf(acc[i][5] + bj[5], 0.f);
            o1.z = fmaxf(acc[i][6] + bj[6], 0.f);
            o1.w = fmaxf(acc[i][7] + bj[7], 0.f);
            *(float4*)&C[(size_t)r * N + col0 + tx * 4]      = o0;
            *(float4*)&C[(size_t)r * N + col0 + 64 + tx * 4] = o1;
        }
    } else {
        // per-thread max over its 8 rows (bias is per-column, so max-then-bias-then-relu OK)
        float cm[8];
#pragma unroll
        for (int j = 0; j < 8; j++) {
            float m = acc[0][j];
#pragma unroll
            for (int i = 1; i < 8; i++) m = fmaxf(m, acc[i][j]);
            cm[j] = fmaxf(m + bj[j], 0.f);
        }
        // block-level reduce over the 16 ty-rows, reusing As as [16][128] scratch
        float (*red)[BM] = As;
#pragma unroll
        for (int j = 0; j < 8; j++) {
            int c = (j < 4) ? (tx * 4 + j) : (64 + tx * 4 + j - 4);
            red[ty][c] = cm[j];
        }
        __syncthreads();
        if (ty == 0) {
            int seg = batch[row0];   // 128-row tile lies within one 4096-row segment
#pragma unroll
            for (int j = 0; j < 8; j++) {
                int c = (j < 4) ? (tx * 4 + j) : (64 + tx * 4 + j - 4);
                float mx = red[0][c];
#pragma unroll
                for (int t = 1; t < 16; t++) mx = fmaxf(mx, red[t][c]);
                atomicMax((int*)&C[(size_t)seg * N + col0 + c], __float_as_int(mx));
            }
        }
    }
}

extern "C" void kernel_launch(void* const* d_in, const int* in_sizes, int n_in,
                              void* d_out, int out_size) {
    const float* x   = (const float*)d_in[0];
    const float* pos = (const float*)d_in[1];
    const int*   bat = (const int*)  d_in[2];
    const float* W1  = (const float*)d_in[3];
    const float* b1  = (const float*)d_in[4];
    const float* W2  = (const float*)d_in[5];
    const float* b2  = (const float*)d_in[6];
    const float* W3  = (const float*)d_in[7];
    const float* b3  = (const float*)d_in[8];
    float* out = (float*)d_out;

    float *h1 = nullptr, *h2 = nullptr;
    cudaGetSymbolAddress((void**)&h1, g_h1);
    cudaGetSymbolAddress((void**)&h2, g_h2);

    // out = 32*1024 floats, poisoned by harness -> zero it (ReLU outputs >= 0)
    zero_out_kernel<<<(out_size + 255) / 256, 256>>>(out, out_size);

    // L1: [131072,259] @ [259,256]
    mlp_gemm<true,  false><<<dim3(256 / BN * 2 / 2, MPTS / BM), 256>>>(
        x, pos, W1, b1, bat, h1, 256, 259, 256);
    // L2: [131072,256] @ [256,512]
    mlp_gemm<false, false><<<dim3(512 / BN, MPTS / BM), 256>>>(
        h1, nullptr, W2, b2, bat, h2, 512, 256, 256);
    // L3 + fused segment max: [131072,512] @ [512,1024] -> max over 4096-row segments
    mlp_gemm<false, true ><<<dim3(1024 / BN, MPTS / BM), 256>>>(
        h2, nullptr, W3, b3, bat, out, 1024, 512, 512);
}

// round 4
// speedup vs baseline: 5.0818x; 5.0818x over previous
#include <cuda_runtime.h>
#include <cstdint>

#define MPTS 131072
#define BM 128
#define BN 128
#define BK 32
#define STAGES 3
#define AP 36                     // A smem row pitch (floats): 144B, 16B-aligned, bank-bijective
#define BP 136                    // B smem row pitch (floats): 544B, 16B-aligned, bank-bijective
#define A_STAGE_F (BM * AP)       // 4608 floats
#define B_STAGE_F (BK * BP)       // 4352 floats
#define SMEM_BYTES (STAGES * (A_STAGE_F + B_STAGE_F) * 4)   // 107520

// ---- scratch (device globals; no allocation allowed) ----
__device__ float g_xr[(size_t)MPTS * 288];    // rounded [x|pos|0] padded to K=288 (151 MB)
__device__ float g_h1[(size_t)MPTS * 256];    // 134 MB
__device__ float g_h2[(size_t)MPTS * 512];    // 268 MB
__device__ float g_w1r[288 * 256];
__device__ float g_w2r[256 * 512];
__device__ float g_w3r[512 * 1024];

// ---------------- helpers ----------------
__device__ __forceinline__ uint32_t s2u(const void* p) {
    uint32_t a;
    asm("{ .reg .u64 t; cvta.to.shared.u64 t, %1; cvt.u32.u64 %0, t; }" : "=r"(a) : "l"(p));
    return a;
}
__device__ __forceinline__ float tf32r(float x) {
    uint32_t u;
    asm("cvt.rna.tf32.f32 %0, %1;" : "=r"(u) : "f"(x));
    return __uint_as_float(u);
}
__device__ __forceinline__ void cp16(uint32_t dst, const void* src) {
    asm volatile("cp.async.cg.shared.global [%0], [%1], 16;" :: "r"(dst), "l"(src));
}
__device__ __forceinline__ void mma8(float* c, const uint32_t* a, const uint32_t* b) {
    asm volatile("mma.sync.aligned.m16n8k8.row.col.f32.tf32.tf32.f32 "
        "{%0,%1,%2,%3}, {%4,%5,%6,%7}, {%8,%9}, {%0,%1,%2,%3};"
        : "+f"(c[0]), "+f"(c[1]), "+f"(c[2]), "+f"(c[3])
        : "r"(a[0]), "r"(a[1]), "r"(a[2]), "r"(a[3]), "r"(b[0]), "r"(b[1]));
}

// ---------------- prep kernels ----------------
__global__ void prep_x_kernel(const float* __restrict__ x, const float* __restrict__ pos,
                              float* __restrict__ xr, float* __restrict__ out, int out_n) {
    int i = blockIdx.x * blockDim.x + threadIdx.x;
    if (i < out_n) out[i] = 0.0f;            // fold output zero-init into this launch
    if (i >= MPTS * 288) return;
    int r = i / 288, c = i % 288;
    float v = 0.0f;
    if (c < 256)      v = tf32r(x[(size_t)r * 256 + c]);
    else if (c < 259) v = tf32r(pos[(size_t)r * 3 + (c - 256)]);
    xr[i] = v;
}
__global__ void wround_kernel(const float* __restrict__ W, float* __restrict__ out,
                              int K, int N, int KP) {
    int i = blockIdx.x * blockDim.x + threadIdx.x;
    if (i >= KP * N) return;
    int k = i / N;
    out[i] = (k < K) ? tf32r(W[i]) : 0.0f;
}

// ---------------- fused GEMM: C = relu(A @ B + bias) ----------------
// A [M, lda] row-major (tf32-rounded), B [K, N] row-major (tf32-rounded)
// SEGMAX=0: store tf32-rounded activations. SEGMAX=1: atomicMax segment epilogue.
template<int SEGMAX>
__global__ __launch_bounds__(256, 2)
void tc_gemm(const float* __restrict__ A, const float* __restrict__ B,
             const float* __restrict__ bias, float* __restrict__ C,
             int N, int lda, int nCh)
{
    extern __shared__ float sm[];
    float* As = sm;
    float* Bs = sm + STAGES * A_STAGE_F;
    const uint32_t sbA = s2u(As), sbB = s2u(Bs);
    const int tid = threadIdx.x;
    const int lane = tid & 31, wid = tid >> 5;
    const int wm = (wid >> 2) * 64;       // warp m offset (2 rows of warps)
    const int wn = (wid & 3) * 32;        // warp n offset (4 cols of warps)
    const int row0 = blockIdx.y * BM, col0 = blockIdx.x * BN;

    float acc[4][4][4];
    #pragma unroll
    for (int i = 0; i < 4; i++)
        #pragma unroll
        for (int j = 0; j < 4; j++)
            #pragma unroll
            for (int k = 0; k < 4; k++) acc[i][j][k] = 0.0f;

    auto load_stage = [&](int kc, int s) {
        const int kb = kc * BK;
        #pragma unroll
        for (int i = 0; i < 4; i++) {
            int idx = i * 256 + tid;
            int r = idx >> 3, c4 = idx & 7;
            cp16(sbA + (s * A_STAGE_F + r * AP + c4 * 4) * 4,
                 &A[(size_t)(row0 + r) * lda + kb + c4 * 4]);
        }
        #pragma unroll
        for (int i = 0; i < 4; i++) {
            int idx = i * 256 + tid;
            int kr = idx >> 5, n4 = idx & 31;
            cp16(sbB + (s * B_STAGE_F + kr * BP + n4 * 4) * 4,
                 &B[(size_t)(kb + kr) * N + col0 + n4 * 4]);
        }
        asm volatile("cp.async.commit_group;" ::: "memory");
    };

    load_stage(0, 0);
    load_stage(1, 1);

    for (int kc = 0; kc < nCh; kc++) {
        if (kc + 1 < nCh) asm volatile("cp.async.wait_group 1;" ::: "memory");
        else              asm volatile("cp.async.wait_group 0;" ::: "memory");
        __syncthreads();
        if (kc + 2 < nCh) load_stage(kc + 2, (kc + 2) % STAGES);

        const float* a_s = As + (kc % STAGES) * A_STAGE_F;
        const float* b_s = Bs + (kc % STAGES) * B_STAGE_F;
        #pragma unroll
        for (int kq = 0; kq < 4; kq++) {
            const int k0 = kq * 8;
            uint32_t af[4][4], bf[4][2];
            #pragma unroll
            for (int im = 0; im < 4; im++) {
                const float* p = a_s + (size_t)(wm + im * 16 + (lane >> 2)) * AP + k0 + (lane & 3);
                af[im][0] = __float_as_uint(p[0]);
                af[im][1] = __float_as_uint(p[8 * AP]);
                af[im][2] = __float_as_uint(p[4]);
                af[im][3] = __float_as_uint(p[8 * AP + 4]);
            }
            #pragma unroll
            for (int in = 0; in < 4; in++) {
                const float* p = b_s + (size_t)(k0 + (lane & 3)) * BP + wn + in * 8 + (lane >> 2);
                bf[in][0] = __float_as_uint(p[0]);
                bf[in][1] = __float_as_uint(p[4 * BP]);
            }
            #pragma unroll
            for (int im = 0; im < 4; im++)
                #pragma unroll
                for (int in = 0; in < 4; in++)
                    mma8(acc[im][in], af[im], bf[in]);
        }
    }

    // ---- epilogue ----
    if (!SEGMAX) {
        #pragma unroll
        for (int in = 0; in < 4; in++) {
            const int c = col0 + wn + in * 8 + (lane & 3) * 2;
            const float b0 = bias[c], b1 = bias[c + 1];
            #pragma unroll
            for (int im = 0; im < 4; im++) {
                const int r1 = row0 + wm + im * 16 + (lane >> 2);
                float2 v1, v2;
                v1.x = tf32r(fmaxf(acc[im][in][0] + b0, 0.f));
                v1.y = tf32r(fmaxf(acc[im][in][1] + b1, 0.f));
                v2.x = tf32r(fmaxf(acc[im][in][2] + b0, 0.f));
                v2.y = tf32r(fmaxf(acc[im][in][3] + b1, 0.f));
                *(float2*)&C[(size_t)r1 * N + c]       = v1;
                *(float2*)&C[(size_t)(r1 + 8) * N + c] = v2;
            }
        }
    } else {
        __syncthreads();                       // done reading smem tiles
        int* smax = (int*)sm;                  // reuse smem: 128 ints
        if (tid < 128) smax[tid] = 0;
        __syncthreads();
        #pragma unroll
        for (int in = 0; in < 4; in++) {
            const int c = col0 + wn + in * 8 + (lane & 3) * 2;
            const float b0 = bias[c], b1 = bias[c + 1];
            #pragma unroll
            for (int p = 0; p < 2; p++) {
                float m = fmaxf(acc[0][in][p], acc[0][in][p + 2]);
                #pragma unroll
                for (int im = 1; im < 4; im++)
                    m = fmaxf(m, fmaxf(acc[im][in][p], acc[im][in][p + 2]));
                m = fmaxf(m + (p ? b1 : b0), 0.f);
                m = fmaxf(m, __shfl_xor_sync(0xFFFFFFFFu, m, 4));
                m = fmaxf(m, __shfl_xor_sync(0xFFFFFFFFu, m, 8));
                m = fmaxf(m, __shfl_xor_sync(0xFFFFFFFFu, m, 16));
                if ((lane >> 2) == 0)
                    atomicMax(&smax[wn + in * 8 + (lane & 3) * 2 + p], __float_as_int(m));
            }
        }
        __syncthreads();
        if (tid < 128) {
            const int seg = row0 >> 12;       // 4096 rows per segment
            atomicMax((int*)&C[(size_t)seg * N + col0 + tid], smax[tid]);
        }
    }
}

// ---------------- launch ----------------
extern "C" void kernel_launch(void* const* d_in, const int* in_sizes, int n_in,
                              void* d_out, int out_size) {
    const float* x   = (const float*)d_in[0];
    const float* pos = (const float*)d_in[1];
    const float* W1  = (const float*)d_in[3];
    const float* b1  = (const float*)d_in[4];
    const float* W2  = (const float*)d_in[5];
    const float* b2  = (const float*)d_in[6];
    const float* W3  = (const float*)d_in[7];
    const float* b3  = (const float*)d_in[8];
    float* out = (float*)d_out;

    float *xr, *h1, *h2, *w1r, *w2r, *w3r;
    cudaGetSymbolAddress((void**)&xr,  g_xr);
    cudaGetSymbolAddress((void**)&h1,  g_h1);
    cudaGetSymbolAddress((void**)&h2,  g_h2);
    cudaGetSymbolAddress((void**)&w1r, g_w1r);
    cudaGetSymbolAddress((void**)&w2r, g_w2r);
    cudaGetSymbolAddress((void**)&w3r, g_w3r);

    cudaFuncSetAttribute(tc_gemm<0>, cudaFuncAttributeMaxDynamicSharedMemorySize, SMEM_BYTES);
    cudaFuncSetAttribute(tc_gemm<1>, cudaFuncAttributeMaxDynamicSharedMemorySize, SMEM_BYTES);

    prep_x_kernel<<<(MPTS * 288 + 255) / 256, 256>>>(x, pos, xr, out, 32 * 1024);
    wround_kernel<<<(288 * 256 + 255) / 256, 256>>>(W1, w1r, 259, 256, 288);
    wround_kernel<<<(256 * 512 + 255) / 256, 256>>>(W2, w2r, 256, 512, 256);
    wround_kernel<<<(512 * 1024 + 255) / 256, 256>>>(W3, w3r, 512, 1024, 512);

    // L1: [131072,288] @ [288,256] -> h1
    tc_gemm<0><<<dim3(256 / BN, MPTS / BM), 256, SMEM_BYTES>>>(xr, w1r, b1, h1, 256, 288, 9);
    // L2: [131072,256] @ [256,512] -> h2
    tc_gemm<0><<<dim3(512 / BN, MPTS / BM), 256, SMEM_BYTES>>>(h1, w2r, b2, h2, 512, 256, 8);
    // L3: [131072,512] @ [512,1024] -> fused segment max -> out[32,1024]
    tc_gemm<1><<<dim3(1024 / BN, MPTS / BM), 256, SMEM_BYTES>>>(h2, w3r, b3, out, 1024, 512, 16);
}